// round 5
// baseline (speedup 1.0000x reference)
#include <cuda_runtime.h>
#include <cuda_fp16.h>
#include <cstdint>

#define NTHREADS 512
#define TM 32

__constant__ float c_HA[6][5] = {
    {0.f, 0.f, 0.f, 0.f, 0.f},
    {0.05f, 0.f, 0.f, 0.f, 0.f},
    {0.01875f, 0.05625f, 0.f, 0.f, 0.f},
    {0.24444444444444444f, -0.93333333333333333f, 0.88888888888888888f, 0.f, 0.f},
    {0.73814967232162782f, -2.89894833155005335f, 2.45572321290182902f, -0.07270233196159122f, 0.f},
    {0.71156881313131313f, -2.68939393939393939f, 2.22660567943586826f, 0.06960227272727273f, -0.06838282589193830f}
};
__constant__ float c_HB[6] = {
    0.02278645833333333f, 0.f, 0.11230907457322552f,
    0.16276041666666666f, -0.08059404481132076f, 0.03273809523809524f
};

// fp16 weights packed in mma fragment order:
// fragment f = (mtile*KSTEPS + kstep), mtile = 16 rows; lane l holds 8 halves
// (one uint4) in exact {a0,a1,a2,a3} .f16x2 register order for mma.m16n8k16.
__device__ __align__(16) __half g_Wp1[256 * 64];    //  64 frags
__device__ __align__(16) __half g_Wp2[256 * 256];   // 256 frags
__device__ __align__(16) __half g_Wp3[256 * 256];   // 256 frags
__device__ __align__(16) __half g_Wp4[64 * 256];    //  64 frags

// ---- SMEM byte offsets ----
#define SM_BIAS  0         // 832 floats = 3328 B  (b1|b2|b3|b4)
#define SM_X0    3328      // [64 k][72 halves] = 9216 B
#define SM_XA    12544     // [256][72 halves] = 36864 B
#define SM_XB    49408     // 36864 B
#define SM_KDZ   86272     // [6][64][33] f32 = 50688 B
#define SM_ZB    136960    // [64][33] f32 = 8448 B
#define SM_EP    145408    // 8448 B
#define SM_RED   153856    // [16][32] f32 = 2048 B
#define SM_KDIV  155904    // [6][32] f32 = 768 B
#define SM_LPT   156672    // 128 B
#define SM_TOTAL 156800

#define XLD 144            // X row stride in bytes (72 halves) — conflict-free ldmatrix

__device__ __forceinline__ uint32_t smem_u32(const void* p) {
    uint32_t a;
    asm("{ .reg .u64 t; cvta.to.shared.u64 t, %1; cvt.u32.u64 %0, t; }" : "=r"(a) : "l"(p));
    return a;
}
__device__ __forceinline__ void ldsm4t(uint32_t addr, uint32_t& r0, uint32_t& r1,
                                       uint32_t& r2, uint32_t& r3) {
    asm volatile("ldmatrix.sync.aligned.m8n8.x4.trans.shared.b16 {%0,%1,%2,%3}, [%4];"
                 : "=r"(r0), "=r"(r1), "=r"(r2), "=r"(r3) : "r"(addr));
}
__device__ __forceinline__ void mma16816(float* c, const uint4& a, uint32_t b0, uint32_t b1) {
    asm volatile("mma.sync.aligned.m16n8k16.row.col.f32.f16.f16.f32 "
                 "{%0,%1,%2,%3}, {%4,%5,%6,%7}, {%8,%9}, {%0,%1,%2,%3};"
                 : "+f"(c[0]), "+f"(c[1]), "+f"(c[2]), "+f"(c[3])
                 : "r"(a.x), "r"(a.y), "r"(a.z), "r"(a.w), "r"(b0), "r"(b1));
}
// tanh = 1 - 2/(exp(2x)+1): 1 MUFU (ex2) + bit-trick Newton reciprocal (FMA pipe)
__device__ __forceinline__ float tanh_fast(float x) {
    float e;
    asm("ex2.approx.f32 %0, %1;" : "=f"(e) : "f"(x * 2.8853900817779268f));
    float q = e + 1.0f;
    float r = __int_as_float(0x7EF311C3 - __float_as_int(q));
    r = r * fmaf(-q, r, 2.f);
    r = r * fmaf(-q, r, 2.f);
    return fmaf(-2.0f, r, 1.0f);
}

// ---- prep: pack fp32 weights into fp16 fragment-major layout ----
__global__ void prep_kernel(const float* __restrict__ W1, const float* __restrict__ W2,
                            const float* __restrict__ W3, const float* __restrict__ W4)
{
    int t = blockIdx.x * blockDim.x + threadIdx.x;
    if (t >= 640 * 32) return;
    int frag = t >> 5, lane = t & 31;
    const float* W; __half* dst; int ksn, ld, fl;
    if (frag < 64)       { W = W1; dst = g_Wp1; ksn = 4;  ld = 64;  fl = frag; }
    else if (frag < 320) { W = W2; dst = g_Wp2; ksn = 16; ld = 256; fl = frag - 64; }
    else if (frag < 576) { W = W3; dst = g_Wp3; ksn = 16; ld = 256; fl = frag - 320; }
    else                 { W = W4; dst = g_Wp4; ksn = 16; ld = 256; fl = frag - 576; }
    int mt = fl / ksn, ks = fl % ksn;
    int g = lane >> 2, j2 = (lane & 3) * 2;
    int r0 = mt * 16 + g, r1 = r0 + 8;
    int c0 = ks * 16 + j2;
    __half h[8];
    h[0] = __float2half_rn(W[r0 * ld + c0]);
    h[1] = __float2half_rn(W[r0 * ld + c0 + 1]);
    h[2] = __float2half_rn(W[r1 * ld + c0]);
    h[3] = __float2half_rn(W[r1 * ld + c0 + 1]);
    h[4] = __float2half_rn(W[r0 * ld + c0 + 8]);
    h[5] = __float2half_rn(W[r0 * ld + c0 + 9]);
    h[6] = __float2half_rn(W[r1 * ld + c0 + 8]);
    h[7] = __float2half_rn(W[r1 * ld + c0 + 9]);
    *(uint4*)(dst + fl * 256 + lane * 8) = *(uint4*)h;
}

// ---- tensor-core GEMM (MT=1): acc[2*NPAIR][4] += Wfrag(16 rows) @ X ----
template<int KSTEPS, int NPAIR>
__device__ __forceinline__ void gemm_tc(const uint4* __restrict__ wf,
                                        uint32_t xaddr, int lane, float* acc)
{
#pragma unroll
    for (int i = 0; i < NPAIR * 8; i++) acc[i] = 0.f;
    uint4 an = wf[lane];
#pragma unroll 4
    for (int ks = 0; ks < KSTEPS; ks++) {
        uint4 ac = an;
        if (ks + 1 < KSTEPS) an = wf[(ks + 1) * 32 + lane];
        uint32_t b[NPAIR * 2][2];
#pragma unroll
        for (int p = 0; p < NPAIR; p++)
            ldsm4t(xaddr + ks * (16 * XLD) + p * 32,
                   b[2 * p][0], b[2 * p][1], b[2 * p + 1][0], b[2 * p + 1][1]);
#pragma unroll
        for (int nb = 0; nb < NPAIR * 2; nb++)
            mma16816(acc + nb * 4, ac, b[nb][0], b[nb][1]);
    }
}

// ---- hidden epilogue: acc(C frag, 16 rows) -> bias+tanh+tangent -> fp16 X tile ----
__device__ __forceinline__ void epi_hidden(const float* acc, char* xout,
                                           const float* bias, int w, int lane)
{
    int g = lane >> 2, j2 = (lane & 3) * 2;
    int r = w * 16 + g;
    float b0 = bias[r], b8 = bias[r + 8];
    char* row0 = xout + r * XLD;
    char* row8 = row0 + 8 * XLD;
#pragma unroll
    for (int nb = 0; nb < 4; nb++) {
        const float* cf = acc + nb * 4;         // fwd cols nb*8+j2
        const float* ct = acc + (nb + 4) * 4;   // tangent cols +32
        int n2 = (nb * 8 + j2) * 2;
        float y0 = tanh_fast(cf[0] + b0), y1 = tanh_fast(cf[1] + b0);
        *(__half2*)(row0 + n2)      = __floats2half2_rn(y0, y1);
        *(__half2*)(row0 + 64 + n2) = __floats2half2_rn((1.f - y0 * y0) * ct[0],
                                                        (1.f - y1 * y1) * ct[1]);
        float y2 = tanh_fast(cf[2] + b8), y3 = tanh_fast(cf[3] + b8);
        *(__half2*)(row8 + n2)      = __floats2half2_rn(y2, y3);
        *(__half2*)(row8 + 64 + n2) = __floats2half2_rn((1.f - y2 * y2) * ct[2],
                                                        (1.f - y3 * y3) * ct[3]);
    }
}

__global__ void __launch_bounds__(NTHREADS, 1)
cnf_kernel(const float* __restrict__ x, const float* __restrict__ eps,
           const float* __restrict__ b1, const float* __restrict__ b2,
           const float* __restrict__ b3, const float* __restrict__ b4,
           float* __restrict__ out)
{
    extern __shared__ char smc[];
    const uint32_t sbase = smem_u32(smc);
    const int tid = threadIdx.x;
    const int w = tid >> 5;
    const int lane = tid & 31;
    const int mbase = blockIdx.x * TM;

    float* bias = (float*)(smc + SM_BIAS);
    char*  x0s  = smc + SM_X0;
    char*  xas  = smc + SM_XA;
    char*  xbs  = smc + SM_XB;
    float* kdz  = (float*)(smc + SM_KDZ);
    float* zb   = (float*)(smc + SM_ZB);
    float* ep   = (float*)(smc + SM_EP);
    float* red  = (float*)(smc + SM_RED);
    float* kdiv = (float*)(smc + SM_KDIV);
    float* lpT  = (float*)(smc + SM_LPT);
    const float* b4s = bias + 768;

    // biases
    if (tid < 256) {
        bias[tid]       = b1[tid];
        bias[256 + tid] = b2[tid];
        bias[512 + tid] = b3[tid];
        if (tid < 64) bias[768 + tid] = b4[tid];
    }
    // state (transposed) + X0 tangent half (= eps, constant across stages)
    for (int e = tid; e < 64 * TM; e += NTHREADS) {
        int d = e & 63, m = e >> 6;
        float xv = x[(mbase + m) * 64 + d];
        float ev = eps[(mbase + m) * 64 + d];
        zb[d * 33 + m] = xv;
        ep[d * 33 + m] = ev;
        *(__half*)(x0s + d * XLD + (32 + m) * 2) = __float2half_rn(ev);
    }
    if (tid < TM) lpT[tid] = 0.f;
    __syncthreads();

    // per-lane ldmatrix base pattern
    const uint32_t xpat = ((lane & 7) + ((lane >> 3) & 1) * 8) * XLD + (lane >> 4) * 16;
    float acc[32];

#pragma unroll 1
    for (int step = 0; step < 4; step++) {
#pragma unroll 1
        for (int s = 0; s < 6; s++) {
            // prologue: X0 fwd cols = z + h*sum a[s][j]*k_j (fp16)
            for (int e = tid; e < 64 * 16; e += NTHREADS) {
                int d = e >> 4, mp = (e & 15) * 2;
                float v0 = zb[d * 33 + mp], v1 = zb[d * 33 + mp + 1];
                for (int j = 0; j < s; j++) {
                    float a = c_HA[s][j];
                    v0 += a * kdz[(j * 64 + d) * 33 + mp];
                    v1 += a * kdz[(j * 64 + d) * 33 + mp + 1];
                }
                *(__half2*)(x0s + d * XLD + mp * 2) = __floats2half2_rn(v0, v1);
            }
            __syncthreads();

            // L1: 256x64 @ K=64  (16 warps x 16 rows)
            gemm_tc<4, 4>((const uint4*)g_Wp1 + (w * 4) * 32,
                          sbase + SM_X0 + xpat, lane, acc);
            epi_hidden(acc, xas, bias, w, lane);
            __syncthreads();
            // L2: 256x64 @ K=256
            gemm_tc<16, 4>((const uint4*)g_Wp2 + (w * 16) * 32,
                           sbase + SM_XA + xpat, lane, acc);
            epi_hidden(acc, xbs, bias + 256, w, lane);
            __syncthreads();
            // L3
            gemm_tc<16, 4>((const uint4*)g_Wp3 + (w * 16) * 32,
                           sbase + SM_XB + xpat, lane, acc);
            epi_hidden(acc, xas, bias + 512, w, lane);
            __syncthreads();
            // L4: 64x64 @ K=256 — warps 0..7: mtile=w>>1, n-half=w&1
            if (w < 8) {
                gemm_tc<16, 2>((const uint4*)g_Wp4 + ((w >> 1) * 16) * 32,
                               sbase + SM_XA + (w & 1) * 64 + xpat, lane, acc);
                int g = lane >> 2, j2 = (lane & 3) * 2;
                int mtile = w >> 1;
                int d0 = mtile * 16 + g;
                if ((w & 1) == 0) {
                    // fwd half: kdz = D + b4
#pragma unroll
                    for (int nb = 0; nb < 4; nb++) {
                        const float* c = acc + nb * 4;
                        int m = nb * 8 + j2;
                        kdz[(s * 64 + d0) * 33 + m]         = c[0] + b4s[d0];
                        kdz[(s * 64 + d0) * 33 + m + 1]     = c[1] + b4s[d0];
                        kdz[(s * 64 + d0 + 8) * 33 + m]     = c[2] + b4s[d0 + 8];
                        kdz[(s * 64 + d0 + 8) * 33 + m + 1] = c[3] + b4s[d0 + 8];
                    }
                } else {
                    // tangent half: partial divergence over this mtile's 16 dims
                    float s0[4], s1[4];
#pragma unroll
                    for (int nb = 0; nb < 4; nb++) {
                        const float* c = acc + nb * 4;
                        int m = nb * 8 + j2;
                        s0[nb] = c[0] * ep[d0 * 33 + m]     + c[2] * ep[(d0 + 8) * 33 + m];
                        s1[nb] = c[1] * ep[d0 * 33 + m + 1] + c[3] * ep[(d0 + 8) * 33 + m + 1];
                    }
#pragma unroll
                    for (int mask = 4; mask <= 16; mask <<= 1) {
#pragma unroll
                        for (int nb = 0; nb < 4; nb++) {
                            s0[nb] += __shfl_xor_sync(0xffffffffu, s0[nb], mask);
                            s1[nb] += __shfl_xor_sync(0xffffffffu, s1[nb], mask);
                        }
                    }
                    if (g == 0) {
#pragma unroll
                        for (int nb = 0; nb < 4; nb++) {
                            int m = nb * 8 + j2;
                            red[mtile * 32 + m]     = s0[nb];
                            red[mtile * 32 + m + 1] = s1[nb];
                        }
                    }
                }
            }
            __syncthreads();
            if (tid < 32)
                kdiv[s * 32 + tid] = red[tid] + red[32 + tid] + red[64 + tid] + red[96 + tid];
            __syncthreads();
        }
        // RK45 combine (b[1] == 0)
        for (int e = tid; e < 64 * TM; e += NTHREADS) {
            int m = e & 31, d = e >> 5;
            float v = zb[d * 33 + m];
            v += c_HB[0] * kdz[(0 * 64 + d) * 33 + m];
            v += c_HB[2] * kdz[(2 * 64 + d) * 33 + m];
            v += c_HB[3] * kdz[(3 * 64 + d) * 33 + m];
            v += c_HB[4] * kdz[(4 * 64 + d) * 33 + m];
            v += c_HB[5] * kdz[(5 * 64 + d) * 33 + m];
            zb[d * 33 + m] = v;
        }
        if (tid < 32) {
            float dv = c_HB[0] * kdiv[tid]
                     + c_HB[2] * kdiv[2 * 32 + tid]
                     + c_HB[3] * kdiv[3 * 32 + tid]
                     + c_HB[4] * kdiv[4 * 32 + tid]
                     + c_HB[5] * kdiv[5 * 32 + tid];
            lpT[tid] -= dv;
        }
        __syncthreads();
    }

    // out = sum_d(-0.5 z^2) - 32*log(2pi) - logpT
    {
        int m = tid & 31, g16 = tid >> 5;
        float p = 0.f;
#pragma unroll
        for (int dd = 0; dd < 4; dd++) {
            float z = zb[(g16 * 4 + dd) * 33 + m];
            p -= 0.5f * z * z;
        }
        red[g16 * 32 + m] = p;
    }
    __syncthreads();
    if (tid < 32) {
        float sum = 0.f;
#pragma unroll
        for (int g16 = 0; g16 < 16; g16++) sum += red[g16 * 32 + tid];
        sum -= 32.f * 1.8378770664093453f;
        out[mbase + tid] = sum - lpT[tid];
    }
}

extern "C" void kernel_launch(void* const* d_in, const int* in_sizes, int n_in,
                              void* d_out, int out_size)
{
    const float* x   = (const float*)d_in[0];
    const float* eps = (const float*)d_in[1];
    const float* W1  = (const float*)d_in[2];
    const float* b1  = (const float*)d_in[3];
    const float* W2  = (const float*)d_in[4];
    const float* b2  = (const float*)d_in[5];
    const float* W3  = (const float*)d_in[6];
    const float* b3  = (const float*)d_in[7];
    const float* W4  = (const float*)d_in[8];
    const float* b4  = (const float*)d_in[9];
    float* out = (float*)d_out;

    prep_kernel<<<(640 * 32 + 255) / 256, 256>>>(W1, W2, W3, W4);

    cudaFuncSetAttribute(cnf_kernel, cudaFuncAttributeMaxDynamicSharedMemorySize, SM_TOTAL);
    cnf_kernel<<<32768 / TM, NTHREADS, SM_TOTAL>>>(x, eps, b1, b2, b3, b4, out);
}

// round 6
// speedup vs baseline: 1.2723x; 1.2723x over previous
#include <cuda_runtime.h>
#include <cuda_fp16.h>
#include <cstdint>

#define NTHREADS 256
#define TM 32

__constant__ float c_HA[6][5] = {
    {0.f, 0.f, 0.f, 0.f, 0.f},
    {0.05f, 0.f, 0.f, 0.f, 0.f},
    {0.01875f, 0.05625f, 0.f, 0.f, 0.f},
    {0.24444444444444444f, -0.93333333333333333f, 0.88888888888888888f, 0.f, 0.f},
    {0.73814967232162782f, -2.89894833155005335f, 2.45572321290182902f, -0.07270233196159122f, 0.f},
    {0.71156881313131313f, -2.68939393939393939f, 2.22660567943586826f, 0.06960227272727273f, -0.06838282589193830f}
};
__constant__ float c_HB[6] = {
    0.02278645833333333f, 0.f, 0.11230907457322552f,
    0.16276041666666666f, -0.08059404481132076f, 0.03273809523809524f
};

// fp16 weights packed in mma fragment order (frag = mtile*KSTEPS + kstep,
// mtile = 16 rows; lane holds one uint4 = {a0,a1,a2,a3} f16x2 regs of m16n8k16).
__device__ __align__(16) __half g_Wp1[256 * 64];
__device__ __align__(16) __half g_Wp2[256 * 256];
__device__ __align__(16) __half g_Wp3[256 * 256];
__device__ __align__(16) __half g_Wp4[64 * 256];

// ---- SMEM layout (<= ~106.4 KB so 2 CTAs fit per SM) ----
#define XLD 144                // X row stride bytes (72 halves) — conflict-free ldmatrix
#define SM_XA    0             // [256][72h] = 36864
#define SM_XB    36864         // [256][72h] = 36864 ; rows 0..63 double as X0
#define SM_X0    SM_XB
#define SM_RED   SM_XB         // [8][32] f32 overlay (XB dead when red is live)
#define SM_KDZ   73728         // fp16 [5][64][32] = 20480
#define SM_ZB    94208         // f32 [64][32] = 8192
#define SM_EP    102400        // fp16 [64][32] = 4096
#define SM_BIAS  106496        // fp16 832 -> 1664
#define SM_KDIV  108160        // f32 [5][32] = 640
#define SM_LPT   108800        // f32 [32] = 128
#define SM_TOTAL 108928

__device__ __forceinline__ uint32_t smem_u32(const void* p) {
    uint32_t a;
    asm("{ .reg .u64 t; cvta.to.shared.u64 t, %1; cvt.u32.u64 %0, t; }" : "=r"(a) : "l"(p));
    return a;
}
__device__ __forceinline__ void ldsm4t(uint32_t addr, uint32_t& r0, uint32_t& r1,
                                       uint32_t& r2, uint32_t& r3) {
    asm volatile("ldmatrix.sync.aligned.m8n8.x4.trans.shared.b16 {%0,%1,%2,%3}, [%4];"
                 : "=r"(r0), "=r"(r1), "=r"(r2), "=r"(r3) : "r"(addr));
}
__device__ __forceinline__ void mma16816(float* c, const uint4& a, uint32_t b0, uint32_t b1) {
    asm volatile("mma.sync.aligned.m16n8k16.row.col.f32.f16.f16.f32 "
                 "{%0,%1,%2,%3}, {%4,%5,%6,%7}, {%8,%9}, {%0,%1,%2,%3};"
                 : "+f"(c[0]), "+f"(c[1]), "+f"(c[2]), "+f"(c[3])
                 : "r"(a.x), "r"(a.y), "r"(a.z), "r"(a.w), "r"(b0), "r"(b1));
}
// tanh = 1 - 2/(exp(2x)+1): 1 MUFU + Newton reciprocal on FMA pipe
__device__ __forceinline__ float tanh_fast(float x) {
    float e;
    asm("ex2.approx.f32 %0, %1;" : "=f"(e) : "f"(x * 2.8853900817779268f));
    float q = e + 1.0f;
    float r = __int_as_float(0x7EF311C3 - __float_as_int(q));
    r = r * fmaf(-q, r, 2.f);
    r = r * fmaf(-q, r, 2.f);
    return fmaf(-2.0f, r, 1.0f);
}

// ---- prep: pack fp32 weights into fp16 fragment-major layout ----
__global__ void prep_kernel(const float* __restrict__ W1, const float* __restrict__ W2,
                            const float* __restrict__ W3, const float* __restrict__ W4)
{
    int t = blockIdx.x * blockDim.x + threadIdx.x;
    if (t >= 640 * 32) return;
    int frag = t >> 5, lane = t & 31;
    const float* W; __half* dst; int ksn, ld, fl;
    if (frag < 64)       { W = W1; dst = g_Wp1; ksn = 4;  ld = 64;  fl = frag; }
    else if (frag < 320) { W = W2; dst = g_Wp2; ksn = 16; ld = 256; fl = frag - 64; }
    else if (frag < 576) { W = W3; dst = g_Wp3; ksn = 16; ld = 256; fl = frag - 320; }
    else                 { W = W4; dst = g_Wp4; ksn = 16; ld = 256; fl = frag - 576; }
    int mt = fl / ksn, ks = fl % ksn;
    int g = lane >> 2, j2 = (lane & 3) * 2;
    int r0 = mt * 16 + g, r1 = r0 + 8;
    int c0 = ks * 16 + j2;
    __half h[8];
    h[0] = __float2half_rn(W[r0 * ld + c0]);
    h[1] = __float2half_rn(W[r0 * ld + c0 + 1]);
    h[2] = __float2half_rn(W[r1 * ld + c0]);
    h[3] = __float2half_rn(W[r1 * ld + c0 + 1]);
    h[4] = __float2half_rn(W[r0 * ld + c0 + 8]);
    h[5] = __float2half_rn(W[r0 * ld + c0 + 9]);
    h[6] = __float2half_rn(W[r1 * ld + c0 + 8]);
    h[7] = __float2half_rn(W[r1 * ld + c0 + 9]);
    *(uint4*)(dst + fl * 256 + lane * 8) = *(uint4*)h;
}

// ---- tensor-core GEMM: acc[MT*2*NPAIR][4]; b-frags in batches of 2 ldsm ----
template<int KSTEPS, int NPAIR, int MT>
__device__ __forceinline__ void gemm_tc(const uint4* __restrict__ wf,
                                        uint32_t xaddr, int lane, float* acc)
{
#pragma unroll
    for (int i = 0; i < MT * NPAIR * 8; i++) acc[i] = 0.f;
    uint4 an[MT];
#pragma unroll
    for (int mt = 0; mt < MT; mt++) an[mt] = wf[mt * KSTEPS * 32 + lane];
#pragma unroll 4
    for (int ks = 0; ks < KSTEPS; ks++) {
        uint4 ac[MT];
#pragma unroll
        for (int mt = 0; mt < MT; mt++) ac[mt] = an[mt];
        if (ks + 1 < KSTEPS) {
#pragma unroll
            for (int mt = 0; mt < MT; mt++) an[mt] = wf[(mt * KSTEPS + ks + 1) * 32 + lane];
        }
#pragma unroll
        for (int ph = 0; ph < NPAIR; ph += 2) {
            uint32_t b0, b1, b2, b3, b4, b5, b6, b7;
            ldsm4t(xaddr + ks * (16 * XLD) + ph * 32, b0, b1, b2, b3);
            ldsm4t(xaddr + ks * (16 * XLD) + (ph + 1) * 32, b4, b5, b6, b7);
#pragma unroll
            for (int mt = 0; mt < MT; mt++) {
                float* am = acc + (mt * NPAIR * 2 + 2 * ph) * 4;
                mma16816(am + 0,  ac[mt], b0, b1);
                mma16816(am + 4,  ac[mt], b2, b3);
                mma16816(am + 8,  ac[mt], b4, b5);
                mma16816(am + 12, ac[mt], b6, b7);
            }
        }
    }
}

// ---- hidden epilogue (MT=2): bias+tanh+tangent -> fp16 X tile ----
__device__ __forceinline__ void epi_hidden(const float* acc, char* xout,
                                           const __half* bias, int w, int lane)
{
    int g = lane >> 2, j2 = (lane & 3) * 2;
#pragma unroll
    for (int mt = 0; mt < 2; mt++) {
        int r = w * 32 + mt * 16 + g;
        float b0 = __half2float(bias[r]), b8 = __half2float(bias[r + 8]);
        char* row0 = xout + r * XLD;
        char* row8 = row0 + 8 * XLD;
#pragma unroll
        for (int nb = 0; nb < 4; nb++) {
            const float* cf = acc + (mt * 8 + nb) * 4;       // fwd cols nb*8+j2
            const float* ct = acc + (mt * 8 + nb + 4) * 4;   // tangent cols +32
            int n2 = (nb * 8 + j2) * 2;
            float y0 = tanh_fast(cf[0] + b0), y1 = tanh_fast(cf[1] + b0);
            *(__half2*)(row0 + n2)      = __floats2half2_rn(y0, y1);
            *(__half2*)(row0 + 64 + n2) = __floats2half2_rn((1.f - y0 * y0) * ct[0],
                                                            (1.f - y1 * y1) * ct[1]);
            float y2 = tanh_fast(cf[2] + b8), y3 = tanh_fast(cf[3] + b8);
            *(__half2*)(row8 + n2)      = __floats2half2_rn(y2, y3);
            *(__half2*)(row8 + 64 + n2) = __floats2half2_rn((1.f - y2 * y2) * ct[2],
                                                            (1.f - y3 * y3) * ct[3]);
        }
    }
}

__global__ void __launch_bounds__(NTHREADS, 2)
cnf_kernel(const float* __restrict__ x, const float* __restrict__ eps,
           const float* __restrict__ b1, const float* __restrict__ b2,
           const float* __restrict__ b3, const float* __restrict__ b4,
           float* __restrict__ out)
{
    extern __shared__ char smc[];
    const uint32_t sbase = smem_u32(smc);
    const int tid = threadIdx.x;
    const int w = tid >> 5;
    const int lane = tid & 31;
    const int mbase = blockIdx.x * TM;

    __half* biash = (__half*)(smc + SM_BIAS);
    char*   x0s   = smc + SM_X0;
    char*   xas   = smc + SM_XA;
    char*   xbs   = smc + SM_XB;
    __half* kdzh  = (__half*)(smc + SM_KDZ);
    float*  zb    = (float*)(smc + SM_ZB);
    __half* eph   = (__half*)(smc + SM_EP);
    float*  red   = (float*)(smc + SM_RED);
    float*  kdiv  = (float*)(smc + SM_KDIV);
    float*  lpT   = (float*)(smc + SM_LPT);
    const __half* b4h = biash + 768;

    // biases (fp16)
    biash[tid]       = __float2half_rn(b1[tid]);
    biash[256 + tid] = __float2half_rn(b2[tid]);
    biash[512 + tid] = __float2half_rn(b3[tid]);
    if (tid < 64) biash[768 + tid] = __float2half_rn(b4[tid]);
    // state transposed: zb fp32, eps fp16
    for (int e = tid; e < 64 * TM; e += NTHREADS) {
        int d = e & 63, m = e >> 6;
        zb[d * 32 + m]  = x[(mbase + m) * 64 + d];
        eph[d * 32 + m] = __float2half_rn(eps[(mbase + m) * 64 + d]);
    }
    if (tid < TM) lpT[tid] = 0.f;
    __syncthreads();

    const uint32_t xpat = ((lane & 7) + ((lane >> 3) & 1) * 8) * XLD + (lane >> 4) * 16;
    float acc[64];

#pragma unroll 1
    for (int step = 0; step < 4; step++) {
#pragma unroll 1
        for (int s = 0; s < 6; s++) {
            // prologue: X0 fwd = z + h*sum a[s][j]*k_j ; X0 tangent = eps (re-write, XB was clobbered)
            for (int e = tid; e < 64 * 16; e += NTHREADS) {
                int d = e >> 4, mp = (e & 15) * 2;
                float v0 = zb[d * 32 + mp], v1 = zb[d * 32 + mp + 1];
                for (int j = 0; j < s; j++) {
                    float a = c_HA[s][j];
                    float2 kk = __half22float2(*(const __half2*)(kdzh + (j * 64 + d) * 32 + mp));
                    v0 += a * kk.x;
                    v1 += a * kk.y;
                }
                *(__half2*)(x0s + d * XLD + mp * 2) = __floats2half2_rn(v0, v1);
                *(__half2*)(x0s + d * XLD + 64 + mp * 2) = *(const __half2*)(eph + d * 32 + mp);
            }
            __syncthreads();

            // L1: 256x64 @ K=64
            gemm_tc<4, 4, 2>((const uint4*)g_Wp1 + (w * 2 * 4) * 32,
                             sbase + SM_X0 + xpat, lane, acc);
            epi_hidden(acc, xas, biash, w, lane);
            __syncthreads();
            // L2: 256x64 @ K=256 (writes XB, clobbers X0 — already consumed)
            gemm_tc<16, 4, 2>((const uint4*)g_Wp2 + (w * 2 * 16) * 32,
                              sbase + SM_XA + xpat, lane, acc);
            epi_hidden(acc, xbs, biash + 256, w, lane);
            __syncthreads();
            // L3
            gemm_tc<16, 4, 2>((const uint4*)g_Wp3 + (w * 2 * 16) * 32,
                              sbase + SM_XB + xpat, lane, acc);
            epi_hidden(acc, xas, biash + 512, w, lane);
            __syncthreads();
            // L4: 64x64 @ K=256 — warp w: mtile=w>>1, n-half=w&1
            gemm_tc<16, 2, 1>((const uint4*)g_Wp4 + ((w >> 1) * 16) * 32,
                              sbase + SM_XA + (w & 1) * 64 + xpat, lane, acc);
            {
                int g = lane >> 2, j2 = (lane & 3) * 2;
                int mtile = w >> 1;
                int d0 = mtile * 16 + g;
                if ((w & 1) == 0) {
                    float bb0 = __half2float(b4h[d0]), bb8 = __half2float(b4h[d0 + 8]);
#pragma unroll
                    for (int nb = 0; nb < 4; nb++) {
                        const float* c = acc + nb * 4;
                        int m = nb * 8 + j2;
                        float v00 = c[0] + bb0, v01 = c[1] + bb0;
                        float v10 = c[2] + bb8, v11 = c[3] + bb8;
                        if (s < 5) {
                            *(__half2*)(kdzh + (s * 64 + d0) * 32 + m)     = __floats2half2_rn(v00, v01);
                            *(__half2*)(kdzh + (s * 64 + d0 + 8) * 32 + m) = __floats2half2_rn(v10, v11);
                        } else {  // fold b5*k6 directly into z
                            zb[d0 * 32 + m]           += c_HB[5] * v00;
                            zb[d0 * 32 + m + 1]       += c_HB[5] * v01;
                            zb[(d0 + 8) * 32 + m]     += c_HB[5] * v10;
                            zb[(d0 + 8) * 32 + m + 1] += c_HB[5] * v11;
                        }
                    }
                } else {
                    // tangent half: partial divergence over this mtile's 16 dims
                    float s0[4], s1[4];
#pragma unroll
                    for (int nb = 0; nb < 4; nb++) {
                        const float* c = acc + nb * 4;
                        int m = nb * 8 + j2;
                        float e00 = __half2float(eph[d0 * 32 + m]);
                        float e01 = __half2float(eph[d0 * 32 + m + 1]);
                        float e10 = __half2float(eph[(d0 + 8) * 32 + m]);
                        float e11 = __half2float(eph[(d0 + 8) * 32 + m + 1]);
                        s0[nb] = c[0] * e00 + c[2] * e10;
                        s1[nb] = c[1] * e01 + c[3] * e11;
                    }
#pragma unroll
                    for (int mask = 4; mask <= 16; mask <<= 1) {
#pragma unroll
                        for (int nb = 0; nb < 4; nb++) {
                            s0[nb] += __shfl_xor_sync(0xffffffffu, s0[nb], mask);
                            s1[nb] += __shfl_xor_sync(0xffffffffu, s1[nb], mask);
                        }
                    }
                    if (g == 0) {
#pragma unroll
                        for (int nb = 0; nb < 4; nb++) {
                            int m = nb * 8 + j2;
                            red[mtile * 32 + m]     = s0[nb];
                            red[mtile * 32 + m + 1] = s1[nb];
                        }
                    }
                }
            }
            __syncthreads();
            if (tid < 32) {
                float sum4 = red[tid] + red[32 + tid] + red[64 + tid] + red[96 + tid];
                if (s < 5) kdiv[s * 32 + tid] = sum4;
                else       lpT[tid] -= c_HB[5] * sum4;
            }
            __syncthreads();
        }
        // RK45 combine: j in {0,2,3,4} from kdz fp16 (b1=0, b5 folded above)
        for (int e = tid; e < 64 * 16; e += NTHREADS) {
            int d = e >> 4, mp = (e & 15) * 2;
            float v0 = zb[d * 32 + mp], v1 = zb[d * 32 + mp + 1];
#pragma unroll
            for (int j = 0; j < 5; j++) {
                if (j == 1) continue;
                float bb = c_HB[j];
                float2 kk = __half22float2(*(const __half2*)(kdzh + (j * 64 + d) * 32 + mp));
                v0 += bb * kk.x;
                v1 += bb * kk.y;
            }
            zb[d * 32 + mp] = v0;
            zb[d * 32 + mp + 1] = v1;
        }
        if (tid < 32) {
            float dv = c_HB[0] * kdiv[tid]
                     + c_HB[2] * kdiv[2 * 32 + tid]
                     + c_HB[3] * kdiv[3 * 32 + tid]
                     + c_HB[4] * kdiv[4 * 32 + tid];
            lpT[tid] -= dv;
        }
        __syncthreads();
    }

    // out = sum_d(-0.5 z^2) - 32*log(2pi) - logpT
    {
        int m = tid & 31, g8 = tid >> 5;
        float p = 0.f;
#pragma unroll
        for (int dd = 0; dd < 8; dd++) {
            float z = zb[(g8 * 8 + dd) * 32 + m];
            p -= 0.5f * z * z;
        }
        red[g8 * 32 + m] = p;
    }
    __syncthreads();
    if (tid < 32) {
        float sum = 0.f;
#pragma unroll
        for (int g8 = 0; g8 < 8; g8++) sum += red[g8 * 32 + tid];
        sum -= 32.f * 1.8378770664093453f;
        out[mbase + tid] = sum - lpT[tid];
    }
}

extern "C" void kernel_launch(void* const* d_in, const int* in_sizes, int n_in,
                              void* d_out, int out_size)
{
    const float* x   = (const float*)d_in[0];
    const float* eps = (const float*)d_in[1];
    const float* W1  = (const float*)d_in[2];
    const float* b1  = (const float*)d_in[3];
    const float* W2  = (const float*)d_in[4];
    const float* b2  = (const float*)d_in[5];
    const float* W3  = (const float*)d_in[6];
    const float* b3  = (const float*)d_in[7];
    const float* W4  = (const float*)d_in[8];
    const float* b4  = (const float*)d_in[9];
    float* out = (float*)d_out;

    prep_kernel<<<(640 * 32 + 255) / 256, 256>>>(W1, W2, W3, W4);

    cudaFuncSetAttribute(cnf_kernel, cudaFuncAttributeMaxDynamicSharedMemorySize, SM_TOTAL);
    cnf_kernel<<<32768 / TM, NTHREADS, SM_TOTAL>>>(x, eps, b1, b2, b3, b4, out);
}